// round 3
// baseline (speedup 1.0000x reference)
#include <cuda_runtime.h>
#include <cuda_bf16.h>
#include <cstdint>

// Problem constants
#define BB 1024
#define RR 8
#define CC 1024
#define DD 16384
#define KK 32
#define NCAND 64

// ---------------- device scratch (allocation-free rule: __device__ globals) ----
__device__ float         g_h  [(size_t)BB * RR * DD];        // 512 MB approx h
__device__ float         g_xc [(size_t)BB * RR * CC];        // 32 MB  x - decoder_b (fp32)
__device__ __nv_bfloat16 g_Ah [(size_t)RR * BB * CC];        // 16 MB  bf16 activations [r][b][c]
__device__ __nv_bfloat16 g_Bh [(size_t)RR * DD * CC];        // 256 MB bf16 enc weights [r][d][c]
__device__ float         g_dwT[(size_t)RR * DD * CC];        // 512 MB decoder_w transposed
__device__ int           g_cand[(size_t)BB * RR * NCAND];    // 2 MB   top-64 candidates
__device__ float         g_vals[(size_t)BB * RR * KK];
__device__ int           g_idx [(size_t)BB * RR * KK];

// ---------------- prep: xc = x - decoder_b (fp32) + bf16 copy -----------------
__global__ void prep_x_kernel(const float* __restrict__ x,
                              const float* __restrict__ db) {
    int idx = blockIdx.x * blockDim.x + threadIdx.x;   // over B*R*C
    int b = idx >> 13;
    int r = (idx >> 10) & 7;
    int c = idx & 1023;
    float xc = x[idx] - db[r * CC + c];
    g_xc[idx] = xc;
    g_Ah[((size_t)r * BB + b) * CC + c] = __float2bfloat16(xc);
}

__global__ void prep_w_kernel(const float* __restrict__ ew) {
    int idx = blockIdx.x * blockDim.x + threadIdx.x;   // over R*D*C
    g_Bh[idx] = __float2bfloat16(ew[idx]);
}

// ---------------- decoder_w transpose: [r][c][d] -> [r][d][c] -----------------
__global__ void transpose_dw_kernel(const float* __restrict__ dw) {
    __shared__ float tile[32][33];
    int d0 = blockIdx.x * 32;
    int c0 = blockIdx.y * 32;
    int r  = blockIdx.z;
    int tx = threadIdx.x, ty = threadIdx.y;   // (32, 8)
    #pragma unroll
    for (int j = 0; j < 4; j++) {
        int c = c0 + ty + j * 8;
        tile[ty + j * 8][tx] = dw[((size_t)r * CC + c) * DD + d0 + tx];
    }
    __syncthreads();
    #pragma unroll
    for (int j = 0; j < 4; j++) {
        int d = d0 + ty + j * 8;
        g_dwT[((size_t)r * DD + d) * CC + c0 + tx] = tile[tx][ty + j * 8];
    }
}

// ---------------- approx encoder GEMM: bf16 mma m16n8k16, K=1024 --------------
#define BB_M 128
#define BB_N 128
#define BB_K 32
#define SST 40     // smem row stride in bf16 (80B: 16B aligned, conflict-free)

__device__ __forceinline__ void mma16816(float* c, const uint32_t* a, const uint32_t* b) {
    asm volatile(
        "mma.sync.aligned.m16n8k16.row.col.f32.bf16.bf16.f32 "
        "{%0,%1,%2,%3}, {%4,%5,%6,%7}, {%8,%9}, {%0,%1,%2,%3};\n"
        : "+f"(c[0]), "+f"(c[1]), "+f"(c[2]), "+f"(c[3])
        : "r"(a[0]), "r"(a[1]), "r"(a[2]), "r"(a[3]), "r"(b[0]), "r"(b[1]));
}

__global__ __launch_bounds__(256, 2)
void encoder_gemm_kernel(const __nv_bfloat16* __restrict__ Ap,
                         const __nv_bfloat16* __restrict__ Bp,
                         const float* __restrict__ eb,
                         float* __restrict__ H) {
    const int mt = blockIdx.x;        // 8 M-tiles
    const int nt = blockIdx.y;        // 128 N-tiles
    const int r  = blockIdx.z;        // 8
    const int tid  = threadIdx.x;
    const int wid  = tid >> 5, lane = tid & 31;
    const int wm = wid >> 2, wn = wid & 3;          // 2 x 4 warps, 64x32 per warp
    const int g = lane >> 2, t = lane & 3;

    __shared__ __nv_bfloat16 sA[2][BB_M * SST];
    __shared__ __nv_bfloat16 sB[2][BB_N * SST];

    float acc[4][4][4];
    #pragma unroll
    for (int i = 0; i < 4; i++)
        #pragma unroll
        for (int j = 0; j < 4; j++)
            #pragma unroll
            for (int q = 0; q < 4; q++) acc[i][j][q] = 0.f;

    const int NKT = CC / BB_K;  // 32
    uint4 ra[2], rb[2];

    const int row0 = tid >> 2, seg0 = tid & 3;
    const int row1 = (tid + 256) >> 2, seg1 = (tid + 256) & 3;
    size_t aBase0 = ((size_t)r * BB + mt * 128 + row0) * CC + seg0 * 8;
    size_t aBase1 = ((size_t)r * BB + mt * 128 + row1) * CC + seg1 * 8;
    size_t bBase0 = ((size_t)r * DD + nt * 128 + row0) * CC + seg0 * 8;
    size_t bBase1 = ((size_t)r * DD + nt * 128 + row1) * CC + seg1 * 8;

    auto loadg = [&](int kt) {
        size_t ko = (size_t)kt * BB_K;
        ra[0] = *(const uint4*)(Ap + aBase0 + ko);
        ra[1] = *(const uint4*)(Ap + aBase1 + ko);
        rb[0] = *(const uint4*)(Bp + bBase0 + ko);
        rb[1] = *(const uint4*)(Bp + bBase1 + ko);
    };
    auto stores = [&](int buf) {
        *(uint4*)(&sA[buf][row0 * SST + seg0 * 8]) = ra[0];
        *(uint4*)(&sA[buf][row1 * SST + seg1 * 8]) = ra[1];
        *(uint4*)(&sB[buf][row0 * SST + seg0 * 8]) = rb[0];
        *(uint4*)(&sB[buf][row1 * SST + seg1 * 8]) = rb[1];
    };

    loadg(0);
    stores(0);
    __syncthreads();

    for (int kt = 0; kt < NKT; kt++) {
        const int buf = kt & 1;
        if (kt + 1 < NKT) loadg(kt + 1);

        #pragma unroll
        for (int ks = 0; ks < 2; ks++) {
            const int ko = ks * 16;
            uint32_t afr[4][4], bfr[4][2];
            #pragma unroll
            for (int mi = 0; mi < 4; mi++) {
                int rowb = wm * 64 + mi * 16;
                afr[mi][0] = *(const uint32_t*)&sA[buf][(rowb + g    ) * SST + ko + 2 * t];
                afr[mi][1] = *(const uint32_t*)&sA[buf][(rowb + g + 8) * SST + ko + 2 * t];
                afr[mi][2] = *(const uint32_t*)&sA[buf][(rowb + g    ) * SST + ko + 8 + 2 * t];
                afr[mi][3] = *(const uint32_t*)&sA[buf][(rowb + g + 8) * SST + ko + 8 + 2 * t];
            }
            #pragma unroll
            for (int ni = 0; ni < 4; ni++) {
                int colb = wn * 32 + ni * 8 + g;
                bfr[ni][0] = *(const uint32_t*)&sB[buf][colb * SST + ko + 2 * t];
                bfr[ni][1] = *(const uint32_t*)&sB[buf][colb * SST + ko + 8 + 2 * t];
            }
            #pragma unroll
            for (int mi = 0; mi < 4; mi++)
                #pragma unroll
                for (int ni = 0; ni < 4; ni++)
                    mma16816(acc[mi][ni], afr[mi], bfr[ni]);
        }

        if (kt + 1 < NKT) stores(1 - buf);
        __syncthreads();
    }

    // epilogue: approx h = acc + encoder_b
    #pragma unroll
    for (int mi = 0; mi < 4; mi++) {
        #pragma unroll
        for (int ni = 0; ni < 4; ni++) {
            int b0 = mt * 128 + wm * 64 + mi * 16 + g;
            int d0 = nt * 128 + wn * 32 + ni * 8 + 2 * t;
            float e0 = eb[(size_t)r * DD + d0];
            float e1 = eb[(size_t)r * DD + d0 + 1];
            size_t o0 = ((size_t)b0 * RR + r) * DD + d0;
            H[o0]     = acc[mi][ni][0] + e0;
            H[o0 + 1] = acc[mi][ni][1] + e1;
            size_t o1 = ((size_t)(b0 + 8) * RR + r) * DD + d0;
            H[o1]     = acc[mi][ni][2] + e0;
            H[o1 + 1] = acc[mi][ni][3] + e1;
        }
    }
}

// ---------------- approx top-64 candidates via 4-pass radix select ------------
__device__ __forceinline__ unsigned f2key(float x) {
    unsigned u = __float_as_uint(x);
    return (u & 0x80000000u) ? ~u : (u | 0x80000000u);
}

__global__ void topk_kernel(const float* __restrict__ H) {
    extern __shared__ unsigned skey[];        // D = 16384 keys (64 KB)
    __shared__ int hist[256];
    __shared__ unsigned s_prefix;
    __shared__ int s_remaining;
    __shared__ int s_cnt, s_tiecnt;
    __shared__ int out_idx[NCAND];
    __shared__ int tie_idx[192];

    const int row = blockIdx.x;               // b*R + r
    const int tid = threadIdx.x;              // 256 threads
    const float* hrow = H + (size_t)row * DD;

    for (int i = tid; i < DD; i += 256) skey[i] = f2key(hrow[i]);
    __syncthreads();

    unsigned prefix = 0;
    int remaining = NCAND;
    for (int shift = 24; shift >= 0; shift -= 8) {
        hist[tid & 255] = 0;
        __syncthreads();
        unsigned pmask = (shift == 24) ? 0u : (0xFFFFFFFFu << (shift + 8));
        for (int i = tid; i < DD; i += 256) {
            unsigned k = skey[i];
            if ((k & pmask) == prefix) atomicAdd(&hist[(k >> shift) & 255], 1);
        }
        __syncthreads();
        if (tid == 0) {
            int cum = 0, v = 255;
            for (; v > 0; v--) {
                if (cum + hist[v] >= remaining) break;
                cum += hist[v];
            }
            s_prefix = prefix | ((unsigned)v << shift);
            s_remaining = remaining - cum;
        }
        __syncthreads();
        prefix = s_prefix;
        remaining = s_remaining;
        __syncthreads();
    }
    const unsigned T = prefix;                // NCAND-th largest key

    if (tid == 0) { s_cnt = 0; s_tiecnt = 0; }
    __syncthreads();
    for (int i = tid; i < DD; i += 256) {
        unsigned k = skey[i];
        if (k > T) {
            int p = atomicAdd(&s_cnt, 1);
            out_idx[p] = i;                   // cnt < NCAND guaranteed
        } else if (k == T) {
            int p = atomicAdd(&s_tiecnt, 1);
            if (p < 192) tie_idx[p] = i;
        }
    }
    __syncthreads();
    if (tid == 0) {
        int gcnt = s_cnt;
        int need = NCAND - gcnt;              // >= 1, <= NCAND <= 192 kept ties
        for (int a = 0; a < need; a++) out_idx[gcnt + a] = tie_idx[a];
    }
    __syncthreads();
    if (tid < NCAND) g_cand[(size_t)row * NCAND + tid] = out_idx[tid];
}

// ---------------- exact fp32 refine of 64 candidates -> top-32 ----------------
__global__ __launch_bounds__(256)
void refine_kernel(const float* __restrict__ ew, const float* __restrict__ eb) {
    __shared__ float sxc[CC];                 // 4 KB xc row
    __shared__ float sval[NCAND];
    __shared__ int   scand[NCAND];

    const int row = blockIdx.x;               // b*R + r
    const int r   = row & 7;
    const int tid = threadIdx.x;
    const int wid = tid >> 5, lane = tid & 31;

    for (int i = tid; i < CC; i += 256) sxc[i] = g_xc[(size_t)row * CC + i];
    if (tid < NCAND) scand[tid] = g_cand[(size_t)row * NCAND + tid];
    __syncthreads();

    const float4* xs4 = (const float4*)sxc;
    // 8 warps x 8 candidates each
    #pragma unroll
    for (int j = 0; j < NCAND / 8; j++) {
        int ci = wid * 8 + j;
        int d = scand[ci];
        const float4* wr = (const float4*)(ew + ((size_t)r * DD + d) * CC);
        float acc = 0.f;
        #pragma unroll
        for (int it = 0; it < 8; it++) {
            float4 a = xs4[it * 32 + lane];
            float4 b = wr[it * 32 + lane];
            acc += a.x * b.x;
            acc += a.y * b.y;
            acc += a.z * b.z;
            acc += a.w * b.w;
        }
        #pragma unroll
        for (int o = 16; o > 0; o >>= 1)
            acc += __shfl_xor_sync(0xFFFFFFFFu, acc, o);
        if (lane == 0) sval[ci] = acc + eb[(size_t)r * DD + d];
    }
    __syncthreads();

    // exact top-32 of 64: rank by (value desc, index asc) — matches jax top_k set
    if (tid < NCAND) {
        float v = sval[tid];
        int   d = scand[tid];
        int rank = 0;
        #pragma unroll
        for (int j = 0; j < NCAND; j++) {
            float vj = sval[j];
            int   dj = scand[j];
            rank += (vj > v) || (vj == v && dj < d);
        }
        if (rank < KK) {
            g_idx [(size_t)row * KK + rank] = d;
            g_vals[(size_t)row * KK + rank] = v > 0.f ? v : 0.f;   // relu
        }
    }
}

// ---------------- sparse decode: out = sum_j val_j * dwT[r][idx_j][:] + db ----
__global__ __launch_bounds__(256)
void decode_kernel(const float* __restrict__ db, float* __restrict__ out) {
    __shared__ float sval[KK];
    __shared__ int   sidx[KK];
    const int b = blockIdx.x;
    const int r = blockIdx.y;
    const int tid = threadIdx.x;
    const size_t row = (size_t)b * RR + r;
    if (tid < KK) {
        sval[tid] = g_vals[row * KK + tid];
        sidx[tid] = g_idx [row * KK + tid];
    }
    __syncthreads();
    const float* dwr = g_dwT + (size_t)r * DD * CC;
    #pragma unroll
    for (int it = 0; it < 4; it++) {
        int c = tid + it * 256;
        float acc = db[r * CC + c];
        #pragma unroll
        for (int j = 0; j < KK; j++)
            acc += sval[j] * dwr[(size_t)sidx[j] * CC + c];
        out[row * CC + c] = acc;
    }
}

// ---------------- launch ------------------------------------------------------
extern "C" void kernel_launch(void* const* d_in, const int* in_sizes, int n_in,
                              void* d_out, int out_size) {
    const float* x  = (const float*)d_in[0];   // [B,R,C]
    const float* ew = (const float*)d_in[1];   // [R,D,C]
    const float* eb = (const float*)d_in[2];   // [R,D]
    const float* dw = (const float*)d_in[3];   // [R,C,D]
    const float* db = (const float*)d_in[4];   // [R,C]
    float* out = (float*)d_out;                // [B,R,C]

    float* h_ptr;          cudaGetSymbolAddress((void**)&h_ptr,  g_h);
    __nv_bfloat16* a_ptr;  cudaGetSymbolAddress((void**)&a_ptr,  g_Ah);
    __nv_bfloat16* b_ptr;  cudaGetSymbolAddress((void**)&b_ptr,  g_Bh);

    cudaFuncSetAttribute(topk_kernel, cudaFuncAttributeMaxDynamicSharedMemorySize, 65536);

    prep_x_kernel<<<(BB * RR * CC) / 256, 256>>>(x, db);
    prep_w_kernel<<<(RR * DD * CC) / 256, 256>>>(ew);
    transpose_dw_kernel<<<dim3(DD / 32, CC / 32, RR), dim3(32, 8)>>>(dw);
    encoder_gemm_kernel<<<dim3(BB / 128, DD / 128, RR), 256>>>(a_ptr, b_ptr, eb, h_ptr);
    topk_kernel<<<BB * RR, 256, 65536>>>(h_ptr);
    refine_kernel<<<BB * RR, 256>>>(ew, eb);
    decode_kernel<<<dim3(BB, RR), 256>>>(db, out);
}